// round 1
// baseline (speedup 1.0000x reference)
#include <cuda_runtime.h>
#include <cstdint>
#include <math.h>

// Scaled dot-product attention, B=4 H=16 S=2048 D=64, fp32 in/out.
// FlashAttention-2 style, tf32 mma.sync tensor cores, fp32 accumulation.

#define BR 64          // query rows per CTA
#define BC 64          // key rows per block
#define DH 64          // head dim
#define PSTR 68        // smem row stride in floats (DH + 4, 16B-aligned rows)
#define NTHREADS 128   // 4 warps
#define S_LEN 2048
#define BH 64          // B*H

__device__ __forceinline__ uint32_t f2tf32(float f) {
    uint32_t r;
    asm("cvt.rna.tf32.f32 %0, %1;" : "=r"(r) : "f"(f));
    return r;
}

__device__ __forceinline__ void mma_tf32(float c[4], const uint32_t a[4], const uint32_t b[2]) {
    asm volatile(
        "mma.sync.aligned.m16n8k8.row.col.f32.tf32.tf32.f32 "
        "{%0,%1,%2,%3}, {%4,%5,%6,%7}, {%8,%9}, {%0,%1,%2,%3};\n"
        : "+f"(c[0]), "+f"(c[1]), "+f"(c[2]), "+f"(c[3])
        : "r"(a[0]), "r"(a[1]), "r"(a[2]), "r"(a[3]),
          "r"(b[0]), "r"(b[1]));
}

__global__ void __launch_bounds__(NTHREADS)
fa2_tf32_kernel(const float* __restrict__ q,
                const float* __restrict__ k,
                const float* __restrict__ v,
                float* __restrict__ out) {
    extern __shared__ float smem[];
    float* Qs = smem;                    // [BR][PSTR]
    float* Ks = Qs + BR * PSTR;         // [BC][PSTR]
    float* Vs = Ks + BC * PSTR;         // [BC][PSTR]
    float* Ps = Vs + BC * PSTR;         // [BR][PSTR]

    const int bh    = blockIdx.y;
    const int qbase = blockIdx.x * BR;

    const float* qp = q   + ((size_t)bh * S_LEN + qbase) * DH;
    const float* kp = k   + (size_t)bh * S_LEN * DH;
    const float* vp = v   + (size_t)bh * S_LEN * DH;
    float*       op = out + ((size_t)bh * S_LEN + qbase) * DH;

    const int tid  = threadIdx.x;
    const int warp = tid >> 5;
    const int lane = tid & 31;
    const int g    = lane >> 2;   // 0..7 : fragment row group
    const int qd   = lane & 3;    // 0..3 : quad within group

    const int r0 = warp * 16 + g;     // first fragment row of this thread
    const int r1 = r0 + 8;            // second fragment row

    // ---- load Q tile (pre-scaled by 1/sqrt(D)) ----
    const float scale = 0.125f;
    #pragma unroll
    for (int i = tid; i < BR * (DH / 4); i += NTHREADS) {
        int r  = i >> 4;       // 16 float4 per row
        int c4 = i & 15;
        float4 t = ((const float4*)(qp + (size_t)r * DH))[c4];
        float* dst = &Qs[r * PSTR + c4 * 4];
        dst[0] = t.x * scale; dst[1] = t.y * scale;
        dst[2] = t.z * scale; dst[3] = t.w * scale;
    }

    // ---- softmax / output state ----
    float o_[8][4];
    #pragma unroll
    for (int nt = 0; nt < 8; ++nt)
        #pragma unroll
        for (int c = 0; c < 4; ++c) o_[nt][c] = 0.0f;
    float m0 = -INFINITY, m1 = -INFINITY;
    float l0 = 0.0f, l1 = 0.0f;

    __syncthreads();

    for (int jb = 0; jb < S_LEN / BC; ++jb) {
        // ---- load K,V tiles ----
        const float* kpb = kp + (size_t)jb * BC * DH;
        const float* vpb = vp + (size_t)jb * BC * DH;
        #pragma unroll
        for (int i = tid; i < BC * (DH / 4); i += NTHREADS) {
            int r  = i >> 4;
            int c4 = i & 15;
            float4 tk = ((const float4*)(kpb + (size_t)r * DH))[c4];
            float4 tv = ((const float4*)(vpb + (size_t)r * DH))[c4];
            *(float4*)&Ks[r * PSTR + c4 * 4] = tk;
            *(float4*)&Vs[r * PSTR + c4 * 4] = tv;
        }
        __syncthreads();

        // ---- S = Q K^T  (warp computes its 16x64 slice) ----
        float s_[8][4];
        #pragma unroll
        for (int nt = 0; nt < 8; ++nt)
            #pragma unroll
            for (int c = 0; c < 4; ++c) s_[nt][c] = 0.0f;

        #pragma unroll
        for (int kk = 0; kk < 8; ++kk) {
            uint32_t a[4];
            a[0] = f2tf32(Qs[r0 * PSTR + kk * 8 + qd]);
            a[1] = f2tf32(Qs[r1 * PSTR + kk * 8 + qd]);
            a[2] = f2tf32(Qs[r0 * PSTR + kk * 8 + qd + 4]);
            a[3] = f2tf32(Qs[r1 * PSTR + kk * 8 + qd + 4]);
            #pragma unroll
            for (int nt = 0; nt < 8; ++nt) {
                uint32_t b[2];
                b[0] = f2tf32(Ks[(nt * 8 + g) * PSTR + kk * 8 + qd]);
                b[1] = f2tf32(Ks[(nt * 8 + g) * PSTR + kk * 8 + qd + 4]);
                mma_tf32(s_[nt], a, b);
            }
        }

        // ---- online softmax on fragments ----
        float mx0 = -INFINITY, mx1 = -INFINITY;
        #pragma unroll
        for (int nt = 0; nt < 8; ++nt) {
            mx0 = fmaxf(mx0, fmaxf(s_[nt][0], s_[nt][1]));
            mx1 = fmaxf(mx1, fmaxf(s_[nt][2], s_[nt][3]));
        }
        mx0 = fmaxf(mx0, __shfl_xor_sync(0xffffffffu, mx0, 1));
        mx0 = fmaxf(mx0, __shfl_xor_sync(0xffffffffu, mx0, 2));
        mx1 = fmaxf(mx1, __shfl_xor_sync(0xffffffffu, mx1, 1));
        mx1 = fmaxf(mx1, __shfl_xor_sync(0xffffffffu, mx1, 2));

        float mn0 = fmaxf(m0, mx0);
        float mn1 = fmaxf(m1, mx1);
        float al0 = __expf(m0 - mn0);
        float al1 = __expf(m1 - mn1);
        m0 = mn0; m1 = mn1;

        float rs0 = 0.0f, rs1 = 0.0f;
        #pragma unroll
        for (int nt = 0; nt < 8; ++nt) {
            s_[nt][0] = __expf(s_[nt][0] - mn0); rs0 += s_[nt][0];
            s_[nt][1] = __expf(s_[nt][1] - mn0); rs0 += s_[nt][1];
            s_[nt][2] = __expf(s_[nt][2] - mn1); rs1 += s_[nt][2];
            s_[nt][3] = __expf(s_[nt][3] - mn1); rs1 += s_[nt][3];
        }
        rs0 += __shfl_xor_sync(0xffffffffu, rs0, 1);
        rs0 += __shfl_xor_sync(0xffffffffu, rs0, 2);
        rs1 += __shfl_xor_sync(0xffffffffu, rs1, 1);
        rs1 += __shfl_xor_sync(0xffffffffu, rs1, 2);
        l0 = l0 * al0 + rs0;
        l1 = l1 * al1 + rs1;

        #pragma unroll
        for (int nt = 0; nt < 8; ++nt) {
            o_[nt][0] *= al0; o_[nt][1] *= al0;
            o_[nt][2] *= al1; o_[nt][3] *= al1;
        }

        // ---- stage P to smem (own 16 rows only -> warp-local sync) ----
        #pragma unroll
        for (int nt = 0; nt < 8; ++nt) {
            Ps[r0 * PSTR + nt * 8 + 2 * qd]     = s_[nt][0];
            Ps[r0 * PSTR + nt * 8 + 2 * qd + 1] = s_[nt][1];
            Ps[r1 * PSTR + nt * 8 + 2 * qd]     = s_[nt][2];
            Ps[r1 * PSTR + nt * 8 + 2 * qd + 1] = s_[nt][3];
        }
        __syncwarp();

        // ---- O += P V ----
        #pragma unroll
        for (int kk = 0; kk < 8; ++kk) {
            uint32_t a[4];
            a[0] = f2tf32(Ps[r0 * PSTR + kk * 8 + qd]);
            a[1] = f2tf32(Ps[r1 * PSTR + kk * 8 + qd]);
            a[2] = f2tf32(Ps[r0 * PSTR + kk * 8 + qd + 4]);
            a[3] = f2tf32(Ps[r1 * PSTR + kk * 8 + qd + 4]);
            #pragma unroll
            for (int nt = 0; nt < 8; ++nt) {
                uint32_t b[2];
                b[0] = f2tf32(Vs[(kk * 8 + qd) * PSTR + nt * 8 + g]);
                b[1] = f2tf32(Vs[(kk * 8 + qd + 4) * PSTR + nt * 8 + g]);
                mma_tf32(o_[nt], a, b);
            }
        }
        __syncthreads();   // all warps done with Ks/Vs before next tile load
    }

    // ---- epilogue: normalize and store ----
    const float inv0 = 1.0f / l0;
    const float inv1 = 1.0f / l1;
    #pragma unroll
    for (int nt = 0; nt < 8; ++nt) {
        float2 w0 = make_float2(o_[nt][0] * inv0, o_[nt][1] * inv0);
        float2 w1 = make_float2(o_[nt][2] * inv1, o_[nt][3] * inv1);
        *(float2*)&op[(size_t)r0 * DH + nt * 8 + 2 * qd] = w0;
        *(float2*)&op[(size_t)r1 * DH + nt * 8 + 2 * qd] = w1;
    }
}

extern "C" void kernel_launch(void* const* d_in, const int* in_sizes, int n_in,
                              void* d_out, int out_size) {
    (void)in_sizes; (void)n_in; (void)out_size;
    const float* q = (const float*)d_in[0];
    const float* k = (const float*)d_in[1];
    const float* v = (const float*)d_in[2];
    float* out = (float*)d_out;

    const int smem_bytes = 4 * BR * PSTR * (int)sizeof(float);  // ~69.6 KB
    cudaFuncSetAttribute(fa2_tf32_kernel,
                         cudaFuncAttributeMaxDynamicSharedMemorySize, smem_bytes);

    dim3 grid(S_LEN / BR, BH);   // (32, 64); x-fastest -> concurrent CTAs share K/V in L2
    fa2_tf32_kernel<<<grid, NTHREADS, smem_bytes>>>(q, k, v, out);
}

// round 2
// speedup vs baseline: 1.3799x; 1.3799x over previous
#include <cuda_runtime.h>
#include <cstdint>
#include <math.h>

// Scaled dot-product attention, B=4 H=16 S=2048 D=64, fp32 in/out.
// FlashAttention-2, tf32 mma.sync, fp32 accum.
// R2: 32 rows/warp (BR=128), tf32 pre-converted in smem, ex2-domain softmax.

#define BR 128         // query rows per CTA
#define BC 64          // key rows per block
#define DH 64          // head dim
#define PSTR 68        // smem row stride (floats), conflict-free quad pattern
#define NTHREADS 128   // 4 warps, 32 rows each
#define S_LEN 2048
#define BH 64

#define LOG2E 1.4426950408889634f

__device__ __forceinline__ uint32_t f2tf32(float f) {
    uint32_t r;
    asm("cvt.rna.tf32.f32 %0, %1;" : "=r"(r) : "f"(f));
    return r;
}

__device__ __forceinline__ float ex2(float x) {
    float y;
    asm("ex2.approx.ftz.f32 %0, %1;" : "=f"(y) : "f"(x));
    return y;
}

__device__ __forceinline__ void mma_tf32(float c[4], const uint32_t a[4], const uint32_t b[2]) {
    asm volatile(
        "mma.sync.aligned.m16n8k8.row.col.f32.tf32.tf32.f32 "
        "{%0,%1,%2,%3}, {%4,%5,%6,%7}, {%8,%9}, {%0,%1,%2,%3};\n"
        : "+f"(c[0]), "+f"(c[1]), "+f"(c[2]), "+f"(c[3])
        : "r"(a[0]), "r"(a[1]), "r"(a[2]), "r"(a[3]),
          "r"(b[0]), "r"(b[1]));
}

__global__ void __launch_bounds__(NTHREADS)
fa2_tf32_kernel(const float* __restrict__ q,
                const float* __restrict__ k,
                const float* __restrict__ v,
                float* __restrict__ out) {
    extern __shared__ uint32_t smem_u[];
    uint32_t* Qs = smem_u;                 // [BR][PSTR] tf32
    uint32_t* Ks = Qs + BR * PSTR;        // [BC][PSTR] tf32
    uint32_t* Vs = Ks + BC * PSTR;        // [BC][PSTR] tf32
    uint32_t* Ps = Vs + BC * PSTR;        // [BR][PSTR] tf32

    const int bh    = blockIdx.y;
    const int qbase = blockIdx.x * BR;

    const float* qp = q   + ((size_t)bh * S_LEN + qbase) * DH;
    const float* kp = k   + (size_t)bh * S_LEN * DH;
    const float* vp = v   + (size_t)bh * S_LEN * DH;
    float*       op = out + ((size_t)bh * S_LEN + qbase) * DH;

    const int tid   = threadIdx.x;
    const int warp  = tid >> 5;
    const int lane  = tid & 31;
    const int g     = lane >> 2;   // 0..7
    const int qd    = lane & 3;    // 0..3
    const int rbase = warp * 32;   // this warp's 32 rows

    // fragment rows for m-tile t: rt0 = rbase + 16t + g, rt1 = rt0 + 8

    // ---- load Q (scaled by log2e/sqrt(D)), convert to tf32 ----
    const float scale = 0.125f * LOG2E;
    #pragma unroll
    for (int i = tid; i < BR * (DH / 4); i += NTHREADS) {
        int r  = i >> 4;
        int c4 = i & 15;
        float4 t = ((const float4*)(qp + (size_t)r * DH))[c4];
        uint32_t* dst = &Qs[r * PSTR + c4 * 4];
        dst[0] = f2tf32(t.x * scale); dst[1] = f2tf32(t.y * scale);
        dst[2] = f2tf32(t.z * scale); dst[3] = f2tf32(t.w * scale);
    }

    float o_[2][8][4];
    #pragma unroll
    for (int t = 0; t < 2; ++t)
        #pragma unroll
        for (int nt = 0; nt < 8; ++nt)
            #pragma unroll
            for (int c = 0; c < 4; ++c) o_[t][nt][c] = 0.0f;
    float m_[2][2] = {{-INFINITY, -INFINITY}, {-INFINITY, -INFINITY}};
    float l_[2][2] = {{0.0f, 0.0f}, {0.0f, 0.0f}};

    __syncthreads();

    for (int jb = 0; jb < S_LEN / BC; ++jb) {
        // ---- load K,V tile, convert to tf32 ----
        const float* kpb = kp + (size_t)jb * BC * DH;
        const float* vpb = vp + (size_t)jb * BC * DH;
        #pragma unroll
        for (int i = tid; i < BC * (DH / 4); i += NTHREADS) {
            int r  = i >> 4;
            int c4 = i & 15;
            float4 tk = ((const float4*)(kpb + (size_t)r * DH))[c4];
            float4 tv = ((const float4*)(vpb + (size_t)r * DH))[c4];
            uint32_t* dk = &Ks[r * PSTR + c4 * 4];
            dk[0] = f2tf32(tk.x); dk[1] = f2tf32(tk.y);
            dk[2] = f2tf32(tk.z); dk[3] = f2tf32(tk.w);
            uint32_t* dv = &Vs[r * PSTR + c4 * 4];
            dv[0] = f2tf32(tv.x); dv[1] = f2tf32(tv.y);
            dv[2] = f2tf32(tv.z); dv[3] = f2tf32(tv.w);
        }
        __syncthreads();

        // ---- S = Q K^T, warp slice 32x64 (scores already in log2 domain) ----
        float s_[2][8][4];
        #pragma unroll
        for (int t = 0; t < 2; ++t)
            #pragma unroll
            for (int nt = 0; nt < 8; ++nt)
                #pragma unroll
                for (int c = 0; c < 4; ++c) s_[t][nt][c] = 0.0f;

        #pragma unroll
        for (int kk = 0; kk < 8; ++kk) {
            uint32_t a[2][4];
            #pragma unroll
            for (int t = 0; t < 2; ++t) {
                int r0 = (rbase + t * 16 + g) * PSTR + kk * 8 + qd;
                a[t][0] = Qs[r0];
                a[t][1] = Qs[r0 + 8 * PSTR];
                a[t][2] = Qs[r0 + 4];
                a[t][3] = Qs[r0 + 8 * PSTR + 4];
            }
            #pragma unroll
            for (int nt = 0; nt < 8; ++nt) {
                uint32_t b[2];
                int kb = (nt * 8 + g) * PSTR + kk * 8 + qd;
                b[0] = Ks[kb];
                b[1] = Ks[kb + 4];
                mma_tf32(s_[0][nt], a[0], b);
                mma_tf32(s_[1][nt], a[1], b);
            }
        }

        // ---- online softmax (base-2) + stage P to smem as tf32 ----
        #pragma unroll
        for (int t = 0; t < 2; ++t) {
            float mx0 = -INFINITY, mx1 = -INFINITY;
            #pragma unroll
            for (int nt = 0; nt < 8; ++nt) {
                mx0 = fmaxf(mx0, fmaxf(s_[t][nt][0], s_[t][nt][1]));
                mx1 = fmaxf(mx1, fmaxf(s_[t][nt][2], s_[t][nt][3]));
            }
            mx0 = fmaxf(mx0, __shfl_xor_sync(0xffffffffu, mx0, 1));
            mx0 = fmaxf(mx0, __shfl_xor_sync(0xffffffffu, mx0, 2));
            mx1 = fmaxf(mx1, __shfl_xor_sync(0xffffffffu, mx1, 1));
            mx1 = fmaxf(mx1, __shfl_xor_sync(0xffffffffu, mx1, 2));

            float mn0 = fmaxf(m_[t][0], mx0);
            float mn1 = fmaxf(m_[t][1], mx1);
            float al0 = ex2(m_[t][0] - mn0);
            float al1 = ex2(m_[t][1] - mn1);
            m_[t][0] = mn0; m_[t][1] = mn1;

            int pr0 = (rbase + t * 16 + g) * PSTR;
            int pr1 = pr0 + 8 * PSTR;

            float rs0 = 0.0f, rs1 = 0.0f;
            #pragma unroll
            for (int nt = 0; nt < 8; ++nt) {
                float p0 = ex2(s_[t][nt][0] - mn0);
                float p1 = ex2(s_[t][nt][1] - mn0);
                float p2 = ex2(s_[t][nt][2] - mn1);
                float p3 = ex2(s_[t][nt][3] - mn1);
                rs0 += p0 + p1;
                rs1 += p2 + p3;
                Ps[pr0 + nt * 8 + 2 * qd]     = f2tf32(p0);
                Ps[pr0 + nt * 8 + 2 * qd + 1] = f2tf32(p1);
                Ps[pr1 + nt * 8 + 2 * qd]     = f2tf32(p2);
                Ps[pr1 + nt * 8 + 2 * qd + 1] = f2tf32(p3);
            }
            rs0 += __shfl_xor_sync(0xffffffffu, rs0, 1);
            rs0 += __shfl_xor_sync(0xffffffffu, rs0, 2);
            rs1 += __shfl_xor_sync(0xffffffffu, rs1, 1);
            rs1 += __shfl_xor_sync(0xffffffffu, rs1, 2);
            l_[t][0] = l_[t][0] * al0 + rs0;
            l_[t][1] = l_[t][1] * al1 + rs1;

            #pragma unroll
            for (int nt = 0; nt < 8; ++nt) {
                o_[t][nt][0] *= al0; o_[t][nt][1] *= al0;
                o_[t][nt][2] *= al1; o_[t][nt][3] *= al1;
            }
        }
        __syncwarp();

        // ---- O += P V ----
        #pragma unroll
        for (int kk = 0; kk < 8; ++kk) {
            uint32_t a[2][4];
            #pragma unroll
            for (int t = 0; t < 2; ++t) {
                int r0 = (rbase + t * 16 + g) * PSTR + kk * 8 + qd;
                a[t][0] = Ps[r0];
                a[t][1] = Ps[r0 + 8 * PSTR];
                a[t][2] = Ps[r0 + 4];
                a[t][3] = Ps[r0 + 8 * PSTR + 4];
            }
            #pragma unroll
            for (int nt = 0; nt < 8; ++nt) {
                uint32_t b[2];
                b[0] = Vs[(kk * 8 + qd) * PSTR + nt * 8 + g];
                b[1] = Vs[(kk * 8 + qd + 4) * PSTR + nt * 8 + g];
                mma_tf32(o_[0][nt], a[0], b);
                mma_tf32(o_[1][nt], a[1], b);
            }
        }
        __syncthreads();   // all warps done with Ks/Vs before next tile load
    }

    // ---- epilogue ----
    #pragma unroll
    for (int t = 0; t < 2; ++t) {
        const float inv0 = 1.0f / l_[t][0];
        const float inv1 = 1.0f / l_[t][1];
        int r0 = rbase + t * 16 + g;
        int r1 = r0 + 8;
        #pragma unroll
        for (int nt = 0; nt < 8; ++nt) {
            float2 w0 = make_float2(o_[t][nt][0] * inv0, o_[t][nt][1] * inv0);
            float2 w1 = make_float2(o_[t][nt][2] * inv1, o_[t][nt][3] * inv1);
            *(float2*)&op[(size_t)r0 * DH + nt * 8 + 2 * qd] = w0;
            *(float2*)&op[(size_t)r1 * DH + nt * 8 + 2 * qd] = w1;
        }
    }
}

extern "C" void kernel_launch(void* const* d_in, const int* in_sizes, int n_in,
                              void* d_out, int out_size) {
    (void)in_sizes; (void)n_in; (void)out_size;
    const float* q = (const float*)d_in[0];
    const float* k = (const float*)d_in[1];
    const float* v = (const float*)d_in[2];
    float* out = (float*)d_out;

    const int smem_bytes = (2 * BR * PSTR + 2 * BC * PSTR) * (int)sizeof(uint32_t); // ~104.4 KB
    cudaFuncSetAttribute(fa2_tf32_kernel,
                         cudaFuncAttributeMaxDynamicSharedMemorySize, smem_bytes);

    dim3 grid(S_LEN / BR, BH);   // (16, 64)
    fa2_tf32_kernel<<<grid, NTHREADS, smem_bytes>>>(q, k, v, out);
}